// round 15
// baseline (speedup 1.0000x reference)
#include <cuda_runtime.h>

// ---------------------------------------------------------------------------
// WaveConv2d via perfect-reconstruction identity:
//   out = x + IDWT( mix(level4 coeffs) - level4 coeffs, 0 elsewhere )
// Round 15: R11 width pass restored (R14's LDS.64 there regressed); load
// phases of fusedAna/anaL4 restructured warp-per-row (hoisted row reflection,
// no div/mod) to cut the dominant ALU address math. Keep fusedSyn f2 loads,
// mixAll f2+FFMA2, synL4@512.
// ---------------------------------------------------------------------------

__constant__ float F_H[12] = {
    0.11154074335008017f,  0.4946238903983854f,   0.7511339080215775f,
    0.3152503517092432f,  -0.22626469396516913f, -0.12976686756709563f,
    0.09750160558707936f,  0.02752286553001629f, -0.031582039318031156f,
    0.0005538422009938016f, 0.004777257511010651f, -0.00107730108499558f};

// highpass analysis: F_G[j] = (j odd ? -F_H[11-j] : F_H[11-j])
__constant__ float F_G[12] = {
    -0.00107730108499558f, -0.004777257511010651f, 0.0005538422009938016f,
     0.031582039318031156f, 0.02752286553001629f, -0.09750160558707936f,
    -0.12976686756709563f,  0.22626469396516913f,  0.3152503517092432f,
    -0.7511339080215775f,   0.4946238903983854f,  -0.11154074335008017f};

// lowpass synthesis taps by output parity: even t: F_H[10-2k], odd t: F_H[11-2k]
__constant__ float SYN_C[2][6] = {
    {0.004777257511010651f, -0.031582039318031156f, 0.09750160558707936f,
     -0.22626469396516913f,  0.7511339080215775f,   0.11154074335008017f},
    {-0.00107730108499558f, 0.0005538422009938016f, 0.02752286553001629f,
     -0.12976686756709563f,  0.3152503517092432f,   0.4946238903983854f}};

// highpass synthesis taps: even t: +F_H[2k+1], odd t: -F_H[2k]
__constant__ float SYN_H[2][6] = {
    {0.4946238903983854f,  0.3152503517092432f, -0.12976686756709563f,
     0.02752286553001629f, 0.0005538422009938016f, -0.00107730108499558f},
    {-0.11154074335008017f, -0.7511339080215775f, 0.22626469396516913f,
     -0.09750160558707936f, 0.031582039318031156f, -0.004777257511010651f}};

// scratch (floats)
__device__ float gB[17572864];   // 256*262*262
__device__ float gD[4734976];    // 256*136*136
__device__ float gE[1401856];    // 256*73x74 (stride 74, chan stride 5476)
__device__ float gF[1401856];    // 256*74*74
__device__ float gLL[451584], gLH[451584], gHL[451584], gHH[451584];
__device__ float gML[451584], gMLH[451584], gMHL[451584], gMHH[451584];

__device__ __forceinline__ int refl(int i, int N) {
    if (i < 0) i = -1 - i;
    if (i >= N) i = 2 * N - 1 - i;
    return i;
}

__device__ __forceinline__ float2 ffma2(float2 a, float2 b, float2 c) {
    float2 d;
    asm("fma.rn.f32x2 %0, %1, %2, %3;"
        : "=l"(*reinterpret_cast<unsigned long long*>(&d))
        : "l"(*reinterpret_cast<unsigned long long*>(&a)),
          "l"(*reinterpret_cast<unsigned long long*>(&b)),
          "l"(*reinterpret_cast<unsigned long long*>(&c)));
    return d;
}

// ---------------------------------------------------------------------------
// Fused lowpass analysis. Tile: 32 out rows x 32 out cols. 256 threads.
// Dyn smem: sIn[74][76] + sMid[74][33] = 32264 B  (7 blocks/SM).
// Load phase: warp-per-row, row reflection hoisted, no div/mod.
// ---------------------------------------------------------------------------
__global__ void fusedAna(const float* __restrict__ in, float* __restrict__ out,
                         int N, int inRS, long inCS,
                         int No, int outRS, long outCS) {
    extern __shared__ float sm[];
    float (*sIn)[76]  = (float(*)[76])sm;
    float (*sMid)[33] = (float(*)[33])(sm + 74 * 76);
    const int c0 = blockIdx.x * 32;
    const int t0 = blockIdx.y * 32;
    const int ch = blockIdx.z;
    const int tid = threadIdx.x;
    const int wp = tid >> 5, lane = tid & 31;
    const float* ip = in + (long)ch * inCS;

    const int g0 = 2 * c0 - 10;
    const bool colInterior = (g0 >= 0) && (g0 + 73 < N);

    if (colInterior) {
        // rows reflected once per row; 37 float2 per row (8B aligned)
        for (int qi = wp; qi < 74; qi += 8) {
            int gr = refl(2 * t0 - 10 + qi, N);
            const float2* src = (const float2*)(ip + (long)gr * inRS + g0);
            float2* dst = (float2*)sIn[qi];
            dst[lane] = src[lane];
            if (lane < 5) dst[lane + 32] = src[lane + 32];
        }
    } else {
        for (int qi = wp; qi < 74; qi += 8) {
            int gr = refl(2 * t0 - 10 + qi, N);
            const float* src = ip + (long)gr * inRS;
            for (int ci = lane; ci < 74; ci += 32)
                sIn[qi][ci] = src[refl(g0 + ci, N)];
        }
    }
    __syncthreads();

    // width pass: 74 rows x 4 col-groups (8 outputs each), sliding 12-window
    for (int task = tid; task < 74 * 4; task += 256) {
        int q = task >> 2, g = task & 3;
        const float* row = sIn[q] + 16 * g;
        float w[12];
#pragma unroll
        for (int j = 0; j < 10; j++) w[j] = row[j];
#pragma unroll
        for (int c = 0; c < 8; c++) {
            w[(10 + 2 * c) % 12] = row[2 * c + 10];
            w[(11 + 2 * c) % 12] = row[2 * c + 11];
            float a0 = 0.f, a1 = 0.f;
#pragma unroll
            for (int j = 0; j < 12; j += 2) {
                a0 += F_H[j]     * w[(2 * c + j) % 12];
                a1 += F_H[j + 1] * w[(2 * c + j + 1) % 12];
            }
            sMid[q][8 * g + c] = a0 + a1;
        }
    }
    __syncthreads();

    // height pass: 32 cols x 8 strips (4 outputs each), sliding window down
    {
        const int c = lane;
        const int s = wp;                // 0..7
        const int base = 8 * s;
        float m[12];
#pragma unroll
        for (int j = 0; j < 10; j++) m[j] = sMid[base + j][c];
#pragma unroll
        for (int k = 0; k < 4; k++) {
            m[(10 + 2 * k) % 12] = sMid[base + 10 + 2 * k][c];
            m[(11 + 2 * k) % 12] = sMid[base + 11 + 2 * k][c];
            float a0 = 0.f, a1 = 0.f;
#pragma unroll
            for (int j = 0; j < 12; j += 2) {
                a0 += F_H[j]     * m[(2 * k + j) % 12];
                a1 += F_H[j + 1] * m[(2 * k + j + 1) % 12];
            }
            int t = t0 + 4 * s + k;
            int cg = c0 + c;
            if (t < No && cg < No)
                out[(long)ch * outCS + (long)t * outRS + cg] = a0 + a1;
        }
    }
}

// ---------------------------------------------------------------------------
// Fused lowpass synthesis, parity-paired, float2 output (+x) path.
// Tile 64x64 out from 37x37 in. in strides (rs, cs) support crop reads.
// Load phase uses float2 gmem reads (m even, rs even on all calls).
// ---------------------------------------------------------------------------
__global__ void fusedSyn(const float* __restrict__ in, float* __restrict__ out,
                         const float* __restrict__ x,
                         int N, long rs, long cs, int M) {
    __shared__ float sIn[37][38];
    __shared__ float sMid[64][38];
    const int c0 = blockIdx.x * 64;
    const int r0 = blockIdx.y * 64;
    const int ch = blockIdx.z;
    const int q0 = r0 >> 1, m0 = c0 >> 1;
    const float* ip = in + (long)ch * cs;

    // load 37 rows x 19 col-pairs (covers cols 0..37 of sIn; col 37 padding)
    for (int idx = threadIdx.x; idx < 37 * 19; idx += blockDim.x) {
        int qi = idx / 19, pi = idx % 19;
        int mi = 2 * pi;
        int q = q0 + qi, m = m0 + mi;
        float2 v;
        if (q < N && m + 1 < N) {
            v = *(const float2*)(ip + (long)q * rs + m);
        } else {
            v.x = (q < N && m < N)     ? ip[(long)q * rs + m]     : 0.f;
            v.y = (q < N && m + 1 < N) ? ip[(long)q * rs + m + 1] : 0.f;
        }
        *(float2*)(&sIn[qi][mi]) = v;
    }
    __syncthreads();

    // height: 32 row-pairs x 37 cols; pair shares the 6 inputs
    for (int idx = threadIdx.x; idx < 32 * 37; idx += blockDim.x) {
        int s = idx / 37, mi = idx % 37;
        float a0 = 0.f, a1 = 0.f;
#pragma unroll
        for (int k = 0; k < 6; k++) {
            float v = sIn[s + k][mi];
            a0 += SYN_C[0][k] * v;
            a1 += SYN_C[1][k] * v;
        }
        sMid[2 * s][mi] = a0;
        sMid[2 * s + 1][mi] = a1;
    }
    __syncthreads();

    // width: 64 rows x 32 col-pairs, float2 stores (c even, M even)
    for (int idx = threadIdx.x; idx < 64 * 32; idx += blockDim.x) {
        int ti = idx >> 5, s = idx & 31;
        float a0 = 0.f, a1 = 0.f;
#pragma unroll
        for (int k = 0; k < 6; k++) {
            float v = sMid[ti][s + k];
            a0 += SYN_C[0][k] * v;
            a1 += SYN_C[1][k] * v;
        }
        int r = r0 + ti, c = c0 + 2 * s;
        if (r < M && c < M) {
            long o = (long)ch * M * M + (long)r * M + c;
            float2 res;
            if (x) {
                float2 xv = *(const float2*)(x + o);
                res.x = a0 + xv.x;
                res.y = a1 + xv.y;
            } else {
                res.x = a0;
                res.y = a1;
            }
            *(float2*)(out + o) = res;
        }
    }
}

// ---------------------------------------------------------------------------
// Merged L4 analysis, 2 blocks/channel (row halves). E at row stride 74,
// channel stride 5476. Dyn smem: sIn[63][95]+sLo[63][43]+sHi[63][43]=45612 B.
// Load phase: warp-per-row, row reflection hoisted.
// ---------------------------------------------------------------------------
__global__ void anaL4(const float* __restrict__ E, float* __restrict__ LL,
                      float* __restrict__ LH, float* __restrict__ HL,
                      float* __restrict__ HH) {
    extern __shared__ float sm[];
    float (*sIn)[95] = (float(*)[95])sm;
    float (*sLo)[43] = (float(*)[43])(sm + 63 * 95);
    float (*sHi)[43] = (float(*)[43])(sm + 63 * 95 + 63 * 43);
    const int ch = blockIdx.x;
    const int h = blockIdx.y;
    const int wp = threadIdx.x >> 5, lane = threadIdx.x & 31;
    const float* ip = E + (long)ch * 5476;

    // load 63 rows x 94 cols: rows reflected once, cols reflected per element
    for (int r = wp; r < 63; r += 8) {
        const float* src = ip + (long)refl(42 * h - 10 + r, 73) * 74;
        for (int c = lane; c < 94; c += 32)
            sIn[r][c] = src[refl(c - 10, 73)];
    }
    __syncthreads();

    // width split on 63 rows
    for (int idx = threadIdx.x; idx < 63 * 42; idx += 256) {
        int q = idx / 42, c = idx % 42;
        float l0 = 0.f, l1 = 0.f, h0 = 0.f, h1 = 0.f;
#pragma unroll
        for (int j = 0; j < 12; j += 2) {
            float v0 = sIn[q][2 * c + j];
            float v1 = sIn[q][2 * c + j + 1];
            l0 += F_H[j] * v0;     l1 += F_H[j + 1] * v1;
            h0 += F_G[j] * v0;     h1 += F_G[j + 1] * v1;
        }
        sLo[q][c] = l0 + l1;
        sHi[q][c] = h0 + h1;
    }
    __syncthreads();

    // height split -> 4 subbands (21 out rows this half)
    for (int idx = threadIdx.x; idx < 21 * 42; idx += 256) {
        int tl = idx / 42, c = idx % 42;
        float ll = 0.f, lh = 0.f, hl = 0.f, hh = 0.f;
#pragma unroll
        for (int j = 0; j < 12; j++) {
            float vl = sLo[2 * tl + j][c];
            float vh = sHi[2 * tl + j][c];
            ll += F_H[j] * vl;
            lh += F_G[j] * vl;
            hl += F_H[j] * vh;
            hh += F_G[j] * vh;
        }
        int t = 21 * h + tl;
        long o = (long)ch * 1764 + (long)t * 42 + c;
        LL[o] = ll; LH[o] = lh; HL[o] = hl; HH[o] = hh;
    }
}

// ---------------------------------------------------------------------------
// Merged L4 synthesis: ML,MLH,MHL,MHH (42x42) -> F (74x74). Block/channel,
// 512 threads.
// ---------------------------------------------------------------------------
__global__ void synL4(const float* __restrict__ ML, const float* __restrict__ MLH,
                      const float* __restrict__ MHL, const float* __restrict__ MHH,
                      float* __restrict__ F) {
    extern __shared__ float sm[];
    float (*sML)[43]  = (float(*)[43])sm;
    float (*sMLH)[43] = (float(*)[43])(sm + 42 * 43);
    float (*sMHL)[43] = (float(*)[43])(sm + 2 * 42 * 43);
    float (*sMHH)[43] = (float(*)[43])(sm + 3 * 42 * 43);
    float (*sLo)[43]  = (float(*)[43])(sm + 4 * 42 * 43);
    float (*sHi)[43]  = (float(*)[43])(sm + 4 * 42 * 43 + 74 * 43);
    const int ch = blockIdx.x;
    const long cb = (long)ch * 1764;

    for (int idx = threadIdx.x; idx < 1764; idx += 512) {
        int r = idx / 42, c = idx % 42;
        sML[r][c]  = ML[cb + idx];
        sMLH[r][c] = MLH[cb + idx];
        sMHL[r][c] = MHL[cb + idx];
        sMHH[r][c] = MHH[cb + idx];
    }
    __syncthreads();

    for (int idx = threadIdx.x; idx < 37 * 42; idx += 512) {
        int s = idx / 42, c = idx % 42;
        float l0 = 0.f, l1 = 0.f, h0 = 0.f, h1 = 0.f;
#pragma unroll
        for (int k = 0; k < 6; k++) {
            float vl = sML[s + k][c],  vlh = sMLH[s + k][c];
            float vh = sMHL[s + k][c], vhh = sMHH[s + k][c];
            l0 += SYN_C[0][k] * vl + SYN_H[0][k] * vlh;
            l1 += SYN_C[1][k] * vl + SYN_H[1][k] * vlh;
            h0 += SYN_C[0][k] * vh + SYN_H[0][k] * vhh;
            h1 += SYN_C[1][k] * vh + SYN_H[1][k] * vhh;
        }
        sLo[2 * s][c] = l0; sLo[2 * s + 1][c] = l1;
        sHi[2 * s][c] = h0; sHi[2 * s + 1][c] = h1;
    }
    __syncthreads();

    for (int idx = threadIdx.x; idx < 74 * 37; idx += 512) {
        int r = idx / 37, s = idx % 37;
        float a0 = 0.f, a1 = 0.f;
#pragma unroll
        for (int k = 0; k < 6; k++) {
            float vl = sLo[r][s + k], vh = sHi[r][s + k];
            a0 += SYN_C[0][k] * vl + SYN_H[0][k] * vh;
            a1 += SYN_C[1][k] * vl + SYN_H[1][k] * vh;
        }
        long o = (long)ch * 74 * 74 + (long)r * 74 + 2 * s;
        F[o] = a0; F[o + 1] = a1;
    }
}

// ---------------------------------------------------------------------------
// Channel mix minus identity, pixel-pair float2 + FFMA2, weights read once.
// grid = (4 pair-chunks, 32 o, 4 bands), 256 threads. 882 pairs per (o,band).
// ---------------------------------------------------------------------------
__global__ void mixAll(const float* __restrict__ LL, const float* __restrict__ LH,
                       const float* __restrict__ HL, const float* __restrict__ HH,
                       float* __restrict__ ML, float* __restrict__ MLH,
                       float* __restrict__ MHL, float* __restrict__ MHH,
                       const float* __restrict__ wyl, const float* __restrict__ wyh) {
    int p2 = blockIdx.x * 256 + threadIdx.x;
    if (p2 >= 882) return;
    int o = blockIdx.y;
    int band = blockIdx.z;
    const float* in; float* outp; const float* w; long wStride2;
    if (band == 0)      { in = LL; outp = ML;  w = wyl;            wStride2 = 882; }
    else if (band == 1) { in = LH; outp = MLH; w = wyh;            wStride2 = 2646; }
    else if (band == 2) { in = HL; outp = MHL; w = wyh + 1764;     wStride2 = 2646; }
    else                { in = HH; outp = MHH; w = wyh + 2 * 1764; wStride2 = 2646; }

    const float2* in2 = (const float2*)in;
    const float2* w2  = (const float2*)w;
    float2* out2 = (float2*)outp;

    float2 acc[8];
#pragma unroll
    for (int b = 0; b < 8; b++) {
        float2 v = in2[((long)b * 32 + o) * 882 + p2];
        acc[b] = make_float2(-v.x, -v.y);
    }
    for (int i = 0; i < 32; i++) {
        float2 wv = w2[((long)i * 32 + o) * wStride2 + p2];
#pragma unroll
        for (int b = 0; b < 8; b++) {
            float2 v = in2[((long)b * 32 + i) * 882 + p2];
            acc[b] = ffma2(v, wv, acc[b]);
        }
    }
#pragma unroll
    for (int b = 0; b < 8; b++)
        out2[((long)b * 32 + o) * 882 + p2] = acc[b];
}

static inline int ceilDiv(int a, int b) { return (a + b - 1) / b; }

extern "C" void kernel_launch(void* const* d_in, const int* in_sizes, int n_in,
                              void* d_out, int out_size) {
    (void)in_sizes; (void)n_in; (void)out_size;
    const float* x   = (const float*)d_in[0];
    const float* wyl = (const float*)d_in[1];
    const float* wyh = (const float*)d_in[2];
    float* out = (float*)d_out;

    float *B,*D,*E,*F,*LL,*LH,*HL,*HH,*ML,*MLH,*MHL,*MHH;
    cudaGetSymbolAddress((void**)&B,  gB);
    cudaGetSymbolAddress((void**)&D,  gD);
    cudaGetSymbolAddress((void**)&E,  gE);
    cudaGetSymbolAddress((void**)&F,  gF);
    cudaGetSymbolAddress((void**)&LL, gLL);
    cudaGetSymbolAddress((void**)&LH, gLH);
    cudaGetSymbolAddress((void**)&HL, gHL);
    cudaGetSymbolAddress((void**)&HH, gHH);
    cudaGetSymbolAddress((void**)&ML, gML);
    cudaGetSymbolAddress((void**)&MLH, gMLH);
    cudaGetSymbolAddress((void**)&MHL, gMHL);
    cudaGetSymbolAddress((void**)&MHH, gMHH);

    const int anaSm   = (74 * 76 + 74 * 33) * 4;            // 32264
    const int anaL4Sm = (63 * 95 + 2 * 63 * 43) * 4;        // 45612
    const int synL4Sm = (4 * 42 * 43 + 2 * 74 * 43) * 4;    // 54352
    cudaFuncSetAttribute(fusedAna, cudaFuncAttributeMaxDynamicSharedMemorySize, anaSm);
    cudaFuncSetAttribute(anaL4,   cudaFuncAttributeMaxDynamicSharedMemorySize, anaL4Sm);
    cudaFuncSetAttribute(synL4,   cudaFuncAttributeMaxDynamicSharedMemorySize, synL4Sm);

    // forward lowpass chain (even row strides for float2-aligned reads)
    fusedAna<<<dim3(9, 9, 256), 256, anaSm>>>(x, B, 512, 512, 512L * 512,
                                              261, 262, 262L * 262);
    fusedAna<<<dim3(5, 5, 256), 256, anaSm>>>(B, D, 261, 262, 262L * 262,
                                              136, 136, 136L * 136);
    fusedAna<<<dim3(3, 3, 256), 256, anaSm>>>(D, E, 136, 136, 136L * 136,
                                              73, 74, 5476);
    // L4 split (2 blocks per channel)
    anaL4<<<dim3(256, 2), 256, anaL4Sm>>>(E, LL, LH, HL, HH);
    // channel mix (weights read once, pixel-pair vectorized)
    mixAll<<<dim3(4, 32, 4), 256>>>(LL, LH, HL, HH, ML, MLH, MHL, MHH, wyl, wyh);
    // inverse
    synL4<<<256, 512, synL4Sm>>>(ML, MLH, MHL, MHH, F);
    fusedSyn<<<dim3(ceilDiv(136, 64), ceilDiv(136, 64), 256), 256>>>(
        F, D, nullptr, 73, 74, 74L * 74, 136);
    fusedSyn<<<dim3(ceilDiv(262, 64), ceilDiv(262, 64), 256), 256>>>(
        D, B, nullptr, 136, 136, 136L * 136, 262);
    fusedSyn<<<dim3(ceilDiv(512, 64), ceilDiv(512, 64), 256), 256>>>(
        B, out, x, 261, 262, 262L * 262, 512);
}

// round 17
// speedup vs baseline: 1.1117x; 1.1117x over previous
#include <cuda_runtime.h>

// ---------------------------------------------------------------------------
// WaveConv2d via perfect-reconstruction identity:
//   out = x + IDWT( mix(level4 coeffs) - level4 coeffs, 0 elsewhere )
// Round 16: exact Round-11 kernels (489us known-good) + ONE change: synL4 and
// L3 fusedSyn merged into per-channel synL34 (F stays in smem, one fewer
// launch). Everything else byte-identical to R11.
// ---------------------------------------------------------------------------

__constant__ float F_H[12] = {
    0.11154074335008017f,  0.4946238903983854f,   0.7511339080215775f,
    0.3152503517092432f,  -0.22626469396516913f, -0.12976686756709563f,
    0.09750160558707936f,  0.02752286553001629f, -0.031582039318031156f,
    0.0005538422009938016f, 0.004777257511010651f, -0.00107730108499558f};

// highpass analysis: F_G[j] = (j odd ? -F_H[11-j] : F_H[11-j])
__constant__ float F_G[12] = {
    -0.00107730108499558f, -0.004777257511010651f, 0.0005538422009938016f,
     0.031582039318031156f, 0.02752286553001629f, -0.09750160558707936f,
    -0.12976686756709563f,  0.22626469396516913f,  0.3152503517092432f,
    -0.7511339080215775f,   0.4946238903983854f,  -0.11154074335008017f};

// lowpass synthesis taps by output parity: even t: F_H[10-2k], odd t: F_H[11-2k]
__constant__ float SYN_C[2][6] = {
    {0.004777257511010651f, -0.031582039318031156f, 0.09750160558707936f,
     -0.22626469396516913f,  0.7511339080215775f,   0.11154074335008017f},
    {-0.00107730108499558f, 0.0005538422009938016f, 0.02752286553001629f,
     -0.12976686756709563f,  0.3152503517092432f,   0.4946238903983854f}};

// highpass synthesis taps: even t: +F_H[2k+1], odd t: -F_H[2k]
__constant__ float SYN_H[2][6] = {
    {0.4946238903983854f,  0.3152503517092432f, -0.12976686756709563f,
     0.02752286553001629f, 0.0005538422009938016f, -0.00107730108499558f},
    {-0.11154074335008017f, -0.7511339080215775f, 0.22626469396516913f,
     -0.09750160558707936f, 0.031582039318031156f, -0.004777257511010651f}};

// scratch (floats)
__device__ float gB[17572864];   // 256*262*262
__device__ float gD[4734976];    // 256*136*136
__device__ float gE[1401856];    // 256*73x74 (stride 74, chan stride 5476)
__device__ float gLL[451584], gLH[451584], gHL[451584], gHH[451584];
__device__ float gML[451584], gMLH[451584], gMHL[451584], gMHH[451584];

__device__ __forceinline__ int refl(int i, int N) {
    if (i < 0) i = -1 - i;
    if (i >= N) i = 2 * N - 1 - i;
    return i;
}

// ---------------------------------------------------------------------------
// Fused lowpass analysis (exact R11). Tile: 32 out rows x 32 out cols.
// 256 threads. Dyn smem: sIn[74][76] + sMid[74][33] = 32264 B (7 blocks/SM).
// ---------------------------------------------------------------------------
__global__ void fusedAna(const float* __restrict__ in, float* __restrict__ out,
                         int N, int inRS, long inCS,
                         int No, int outRS, long outCS) {
    extern __shared__ float sm[];
    float (*sIn)[76]  = (float(*)[76])sm;
    float (*sMid)[33] = (float(*)[33])(sm + 74 * 76);
    const int c0 = blockIdx.x * 32;
    const int t0 = blockIdx.y * 32;
    const int ch = blockIdx.z;
    const int tid = threadIdx.x;
    const float* ip = in + (long)ch * inCS;

    const int g0 = 2 * c0 - 10;
    const bool colInterior = (g0 >= 0) && (g0 + 73 < N);

    if (colInterior) {
        for (int idx = tid; idx < 74 * 37; idx += 256) {
            int qi = idx / 37, pi = idx % 37;
            int gr = refl(2 * t0 - 10 + qi, N);
            float2 v = *(const float2*)(ip + (long)gr * inRS + g0 + 2 * pi);
            *(float2*)(&sIn[qi][2 * pi]) = v;
        }
    } else {
        for (int idx = tid; idx < 74 * 74; idx += 256) {
            int qi = idx / 74, ci = idx % 74;
            int gr = refl(2 * t0 - 10 + qi, N);
            int gc = refl(g0 + ci, N);
            sIn[qi][ci] = ip[(long)gr * inRS + gc];
        }
    }
    __syncthreads();

    // width pass: 74 rows x 4 col-groups (8 outputs each), sliding 12-window
    for (int task = tid; task < 74 * 4; task += 256) {
        int q = task >> 2, g = task & 3;
        const float* row = sIn[q] + 16 * g;
        float w[12];
#pragma unroll
        for (int j = 0; j < 10; j++) w[j] = row[j];
#pragma unroll
        for (int c = 0; c < 8; c++) {
            w[(10 + 2 * c) % 12] = row[2 * c + 10];
            w[(11 + 2 * c) % 12] = row[2 * c + 11];
            float a0 = 0.f, a1 = 0.f;
#pragma unroll
            for (int j = 0; j < 12; j += 2) {
                a0 += F_H[j]     * w[(2 * c + j) % 12];
                a1 += F_H[j + 1] * w[(2 * c + j + 1) % 12];
            }
            sMid[q][8 * g + c] = a0 + a1;
        }
    }
    __syncthreads();

    // height pass: 32 cols x 8 strips (4 outputs each), sliding window down
    {
        const int c = tid & 31;
        const int s = tid >> 5;          // 0..7
        const int base = 8 * s;
        float m[12];
#pragma unroll
        for (int j = 0; j < 10; j++) m[j] = sMid[base + j][c];
#pragma unroll
        for (int k = 0; k < 4; k++) {
            m[(10 + 2 * k) % 12] = sMid[base + 10 + 2 * k][c];
            m[(11 + 2 * k) % 12] = sMid[base + 11 + 2 * k][c];
            float a0 = 0.f, a1 = 0.f;
#pragma unroll
            for (int j = 0; j < 12; j += 2) {
                a0 += F_H[j]     * m[(2 * k + j) % 12];
                a1 += F_H[j + 1] * m[(2 * k + j + 1) % 12];
            }
            int t = t0 + 4 * s + k;
            int cg = c0 + c;
            if (t < No && cg < No)
                out[(long)ch * outCS + (long)t * outRS + cg] = a0 + a1;
        }
    }
}

// ---------------------------------------------------------------------------
// Fused lowpass synthesis (exact R11), parity-paired, float2 output (+x) path.
// Tile 64x64 out from 37x37 in. in strides (rs, cs) support crop reads.
// ---------------------------------------------------------------------------
__global__ void fusedSyn(const float* __restrict__ in, float* __restrict__ out,
                         const float* __restrict__ x,
                         int N, long rs, long cs, int M) {
    __shared__ float sIn[37][38];
    __shared__ float sMid[64][38];
    const int c0 = blockIdx.x * 64;
    const int r0 = blockIdx.y * 64;
    const int ch = blockIdx.z;
    const int q0 = r0 >> 1, m0 = c0 >> 1;
    const float* ip = in + (long)ch * cs;

    for (int idx = threadIdx.x; idx < 37 * 37; idx += blockDim.x) {
        int qi = idx / 37, mi = idx % 37;
        int q = q0 + qi, m = m0 + mi;
        sIn[qi][mi] = (q < N && m < N) ? ip[(long)q * rs + m] : 0.f;
    }
    __syncthreads();

    for (int idx = threadIdx.x; idx < 32 * 37; idx += blockDim.x) {
        int s = idx / 37, mi = idx % 37;
        float a0 = 0.f, a1 = 0.f;
#pragma unroll
        for (int k = 0; k < 6; k++) {
            float v = sIn[s + k][mi];
            a0 += SYN_C[0][k] * v;
            a1 += SYN_C[1][k] * v;
        }
        sMid[2 * s][mi] = a0;
        sMid[2 * s + 1][mi] = a1;
    }
    __syncthreads();

    for (int idx = threadIdx.x; idx < 64 * 32; idx += blockDim.x) {
        int ti = idx >> 5, s = idx & 31;
        float a0 = 0.f, a1 = 0.f;
#pragma unroll
        for (int k = 0; k < 6; k++) {
            float v = sMid[ti][s + k];
            a0 += SYN_C[0][k] * v;
            a1 += SYN_C[1][k] * v;
        }
        int r = r0 + ti, c = c0 + 2 * s;
        if (r < M && c < M) {
            long o = (long)ch * M * M + (long)r * M + c;
            float2 res;
            if (x) {
                float2 xv = *(const float2*)(x + o);
                res.x = a0 + xv.x;
                res.y = a1 + xv.y;
            } else {
                res.x = a0;
                res.y = a1;
            }
            *(float2*)(out + o) = res;
        }
    }
}

// ---------------------------------------------------------------------------
// Merged L4 analysis (exact R11), 2 blocks/channel (row halves). E at row
// stride 74, chan stride 5476. Dyn smem: 63*95 + 2*63*43 floats = 45612 B.
// ---------------------------------------------------------------------------
__global__ void anaL4(const float* __restrict__ E, float* __restrict__ LL,
                      float* __restrict__ LH, float* __restrict__ HL,
                      float* __restrict__ HH) {
    extern __shared__ float sm[];
    float (*sIn)[95] = (float(*)[95])sm;
    float (*sLo)[43] = (float(*)[43])(sm + 63 * 95);
    float (*sHi)[43] = (float(*)[43])(sm + 63 * 95 + 63 * 43);
    const int ch = blockIdx.x;
    const int h = blockIdx.y;
    const float* ip = E + (long)ch * 5476;

    for (int idx = threadIdx.x; idx < 63 * 94; idx += 256) {
        int qi = idx / 94, ci = idx % 94;
        sIn[qi][ci] = ip[(long)refl(42 * h - 10 + qi, 73) * 74 + refl(ci - 10, 73)];
    }
    __syncthreads();

    for (int idx = threadIdx.x; idx < 63 * 42; idx += 256) {
        int q = idx / 42, c = idx % 42;
        float l0 = 0.f, l1 = 0.f, h0 = 0.f, h1 = 0.f;
#pragma unroll
        for (int j = 0; j < 12; j += 2) {
            float v0 = sIn[q][2 * c + j];
            float v1 = sIn[q][2 * c + j + 1];
            l0 += F_H[j] * v0;     l1 += F_H[j + 1] * v1;
            h0 += F_G[j] * v0;     h1 += F_G[j + 1] * v1;
        }
        sLo[q][c] = l0 + l1;
        sHi[q][c] = h0 + h1;
    }
    __syncthreads();

    for (int idx = threadIdx.x; idx < 21 * 42; idx += 256) {
        int tl = idx / 42, c = idx % 42;
        float ll = 0.f, lh = 0.f, hl = 0.f, hh = 0.f;
#pragma unroll
        for (int j = 0; j < 12; j++) {
            float vl = sLo[2 * tl + j][c];
            float vh = sHi[2 * tl + j][c];
            ll += F_H[j] * vl;
            lh += F_G[j] * vl;
            hl += F_H[j] * vh;
            hh += F_G[j] * vh;
        }
        int t = 21 * h + tl;
        long o = (long)ch * 1764 + (long)t * 42 + c;
        LL[o] = ll; LH[o] = lh; HL[o] = hl; HH[o] = hh;
    }
}

// ---------------------------------------------------------------------------
// NEW: merged L4+L3 synthesis, one block per channel, 512 threads.
// Subbands (42x42 x4) -> F (74x74, smem only) -> D (136x136, gmem).
// Smem union (floats):
//   [0      .. 7223 ]  sML/sMLH/sMHL/sMHH (4 x 42x43)   } overlapped later
//   [7224   .. 13587]  sLo/sHi (2 x 74x43)              }  by sMid (136x75)
//   [13588  .. 19137]  sF (74x75)
// Total 19138 floats = 76552 B (2 blocks/SM; grid 256 = single wave).
// ---------------------------------------------------------------------------
__global__ void synL34(const float* __restrict__ ML, const float* __restrict__ MLH,
                       const float* __restrict__ MHL, const float* __restrict__ MHH,
                       float* __restrict__ D) {
    extern __shared__ float sm[];
    float (*sML)[43]  = (float(*)[43])sm;
    float (*sMLH)[43] = (float(*)[43])(sm + 1806);
    float (*sMHL)[43] = (float(*)[43])(sm + 3612);
    float (*sMHH)[43] = (float(*)[43])(sm + 5418);
    float (*sLo)[43]  = (float(*)[43])(sm + 7224);
    float (*sHi)[43]  = (float(*)[43])(sm + 10406);
    float (*sF)[75]   = (float(*)[75])(sm + 13588);
    float (*sMid)[75] = (float(*)[75])sm;   // overlaps dead sM*/sLo/sHi regions
    const int ch = blockIdx.x;
    const long cb = (long)ch * 1764;

    // P1: load 4 subband tiles
    for (int idx = threadIdx.x; idx < 1764; idx += 512) {
        int r = idx / 42, c = idx % 42;
        sML[r][c]  = ML[cb + idx];
        sMLH[r][c] = MLH[cb + idx];
        sMHL[r][c] = MHL[cb + idx];
        sMHH[r][c] = MHH[cb + idx];
    }
    __syncthreads();

    // P2: L4 height synthesis -> sLo, sHi (74 x 42)
    for (int idx = threadIdx.x; idx < 37 * 42; idx += 512) {
        int s = idx / 42, c = idx % 42;
        float l0 = 0.f, l1 = 0.f, h0 = 0.f, h1 = 0.f;
#pragma unroll
        for (int k = 0; k < 6; k++) {
            float vl = sML[s + k][c],  vlh = sMLH[s + k][c];
            float vh = sMHL[s + k][c], vhh = sMHH[s + k][c];
            l0 += SYN_C[0][k] * vl + SYN_H[0][k] * vlh;
            l1 += SYN_C[1][k] * vl + SYN_H[1][k] * vlh;
            h0 += SYN_C[0][k] * vh + SYN_H[0][k] * vhh;
            h1 += SYN_C[1][k] * vh + SYN_H[1][k] * vhh;
        }
        sLo[2 * s][c] = l0; sLo[2 * s + 1][c] = l1;
        sHi[2 * s][c] = h0; sHi[2 * s + 1][c] = h1;
    }
    __syncthreads();

    // P3: L4 width synthesis -> sF (74 x 74)
    for (int idx = threadIdx.x; idx < 74 * 37; idx += 512) {
        int r = idx / 37, s = idx % 37;
        float a0 = 0.f, a1 = 0.f;
#pragma unroll
        for (int k = 0; k < 6; k++) {
            float vl = sLo[r][s + k], vh = sHi[r][s + k];
            a0 += SYN_C[0][k] * vl + SYN_H[0][k] * vh;
            a1 += SYN_C[1][k] * vl + SYN_H[1][k] * vh;
        }
        sF[r][2 * s] = a0;
        sF[r][2 * s + 1] = a1;
    }
    __syncthreads();

    // P4: L3 height synthesis on cropped F (73x73) -> sMid (136 x 73)
    // (sMid overlaps sM*/sLo/sHi, all dead after P3)
    for (int idx = threadIdx.x; idx < 68 * 73; idx += 512) {
        int s = idx / 73, m = idx % 73;
        float a0 = 0.f, a1 = 0.f;
#pragma unroll
        for (int k = 0; k < 6; k++) {
            int q = s + k;                 // <= 72, cropped F rows
            float v = (q < 73) ? sF[q][m] : 0.f;
            a0 += SYN_C[0][k] * v;
            a1 += SYN_C[1][k] * v;
        }
        sMid[2 * s][m] = a0;
        sMid[2 * s + 1][m] = a1;
    }
    __syncthreads();

    // P5: L3 width synthesis -> D (136 x 136) gmem, float2 stores
    float* op = D + (long)ch * 136 * 136;
    for (int idx = threadIdx.x; idx < 136 * 68; idx += 512) {
        int r = idx / 68, s = idx % 68;
        float a0 = 0.f, a1 = 0.f;
#pragma unroll
        for (int k = 0; k < 6; k++) {
            int m = s + k;                 // <= 72
            float v = (m < 73) ? sMid[r][m] : 0.f;
            a0 += SYN_C[0][k] * v;
            a1 += SYN_C[1][k] * v;
        }
        float2 res = make_float2(a0, a1);
        *(float2*)(op + (long)r * 136 + 2 * s) = res;
    }
}

// ---------------------------------------------------------------------------
// Channel mix minus identity (exact R11), weights read once from DRAM.
// grid = (7 pixel-chunks, 32 o, 4 bands), 256 threads.
// ---------------------------------------------------------------------------
__global__ void mixAll(const float* __restrict__ LL, const float* __restrict__ LH,
                       const float* __restrict__ HL, const float* __restrict__ HH,
                       float* __restrict__ ML, float* __restrict__ MLH,
                       float* __restrict__ MHL, float* __restrict__ MHH,
                       const float* __restrict__ wyl, const float* __restrict__ wyh) {
    int p = blockIdx.x * 256 + threadIdx.x;
    if (p >= 1764) return;
    int o = blockIdx.y;
    int band = blockIdx.z;
    const float* in; float* outp; const float* w; long ioStride;
    if (band == 0)      { in = LL; outp = ML;  w = wyl;            ioStride = 1764; }
    else if (band == 1) { in = LH; outp = MLH; w = wyh;            ioStride = 5292; }
    else if (band == 2) { in = HL; outp = MHL; w = wyh + 1764;     ioStride = 5292; }
    else                { in = HH; outp = MHH; w = wyh + 2 * 1764; ioStride = 5292; }

    float acc[8];
#pragma unroll
    for (int b = 0; b < 8; b++) acc[b] = -in[((long)b * 32 + o) * 1764 + p];
    for (int i = 0; i < 32; i++) {
        float wv = w[((long)i * 32 + o) * ioStride + p];
#pragma unroll
        for (int b = 0; b < 8; b++)
            acc[b] += in[((long)b * 32 + i) * 1764 + p] * wv;
    }
#pragma unroll
    for (int b = 0; b < 8; b++) outp[((long)b * 32 + o) * 1764 + p] = acc[b];
}

static inline int ceilDiv(int a, int b) { return (a + b - 1) / b; }

extern "C" void kernel_launch(void* const* d_in, const int* in_sizes, int n_in,
                              void* d_out, int out_size) {
    (void)in_sizes; (void)n_in; (void)out_size;
    const float* x   = (const float*)d_in[0];
    const float* wyl = (const float*)d_in[1];
    const float* wyh = (const float*)d_in[2];
    float* out = (float*)d_out;

    float *B,*D,*E,*LL,*LH,*HL,*HH,*ML,*MLH,*MHL,*MHH;
    cudaGetSymbolAddress((void**)&B,  gB);
    cudaGetSymbolAddress((void**)&D,  gD);
    cudaGetSymbolAddress((void**)&E,  gE);
    cudaGetSymbolAddress((void**)&LL, gLL);
    cudaGetSymbolAddress((void**)&LH, gLH);
    cudaGetSymbolAddress((void**)&HL, gHL);
    cudaGetSymbolAddress((void**)&HH, gHH);
    cudaGetSymbolAddress((void**)&ML, gML);
    cudaGetSymbolAddress((void**)&MLH, gMLH);
    cudaGetSymbolAddress((void**)&MHL, gMHL);
    cudaGetSymbolAddress((void**)&MHH, gMHH);

    const int anaSm   = (74 * 76 + 74 * 33) * 4;            // 32264
    const int anaL4Sm = (63 * 95 + 2 * 63 * 43) * 4;        // 45612
    const int synL34Sm = 19138 * 4;                         // 76552
    cudaFuncSetAttribute(fusedAna, cudaFuncAttributeMaxDynamicSharedMemorySize, anaSm);
    cudaFuncSetAttribute(anaL4,   cudaFuncAttributeMaxDynamicSharedMemorySize, anaL4Sm);
    cudaFuncSetAttribute(synL34,  cudaFuncAttributeMaxDynamicSharedMemorySize, synL34Sm);

    // forward lowpass chain (even row strides for float2-aligned reads)
    fusedAna<<<dim3(9, 9, 256), 256, anaSm>>>(x, B, 512, 512, 512L * 512,
                                              261, 262, 262L * 262);
    fusedAna<<<dim3(5, 5, 256), 256, anaSm>>>(B, D, 261, 262, 262L * 262,
                                              136, 136, 136L * 136);
    fusedAna<<<dim3(3, 3, 256), 256, anaSm>>>(D, E, 136, 136, 136L * 136,
                                              73, 74, 5476);
    // L4 split (2 blocks per channel)
    anaL4<<<dim3(256, 2), 256, anaL4Sm>>>(E, LL, LH, HL, HH);
    // channel mix (weights read once)
    mixAll<<<dim3(7, 32, 4), 256>>>(LL, LH, HL, HH, ML, MLH, MHL, MHH, wyl, wyh);
    // inverse: merged L4+L3 synthesis -> D, then L2, L1
    synL34<<<256, 512, synL34Sm>>>(ML, MLH, MHL, MHH, D);
    fusedSyn<<<dim3(ceilDiv(262, 64), ceilDiv(262, 64), 256), 256>>>(
        D, B, nullptr, 136, 136, 136L * 136, 262);
    fusedSyn<<<dim3(ceilDiv(512, 64), ceilDiv(512, 64), 256), 256>>>(
        B, out, x, 261, 262, 262L * 262, 512);
}